// round 1
// baseline (speedup 1.0000x reference)
#include <cuda_runtime.h>

#define SLEN 256
#define BSZ 8
#define NH 16
#define DH 64
#define IND 1024
#define ROWS (SLEN*BSZ) /* 2048 */

// ---- scratch (no allocs allowed -> device globals) ----
__device__ float g_ys[ROWS * IND];   // scan outputs, GEMM A operand (8 MB)
__device__ float g_mu[ROWS];
__device__ float g_rs[ROWS];

// ---- f32x2 helpers (sm_103a packed fp32 FMA, PTX-only) ----
__device__ __forceinline__ unsigned long long pack2(float lo, float hi) {
    unsigned long long r;
    asm("mov.b64 %0, {%1,%2};" : "=l"(r) : "f"(lo), "f"(hi));
    return r;
}
__device__ __forceinline__ void unpack2(unsigned long long v, float& lo, float& hi) {
    asm("mov.b64 {%0,%1}, %2;" : "=f"(lo), "=f"(hi) : "l"(v));
}
__device__ __forceinline__ unsigned long long ffma2(unsigned long long a,
                                                    unsigned long long b,
                                                    unsigned long long c) {
    unsigned long long d;
    asm("fma.rn.f32x2 %0, %1, %2, %3;" : "=l"(d) : "l"(a), "l"(b), "l"(c));
    return d;
}

// ============================================================
// Kernel 1: LayerNorm row stats (mu, 1/sigma) — one warp per row
// ============================================================
__global__ __launch_bounds__(256) void ln_stats_kernel(const float* __restrict__ h) {
    int row  = blockIdx.x * 8 + (threadIdx.x >> 5);
    int lane = threadIdx.x & 31;
    const float* p = h + (size_t)row * IND;
    float s = 0.f, s2 = 0.f;
    #pragma unroll 8
    for (int c = lane; c < IND; c += 32) {
        float v = p[c];
        s += v;
        s2 = fmaf(v, v, s2);
    }
    #pragma unroll
    for (int o = 16; o; o >>= 1) {
        s  += __shfl_xor_sync(0xffffffffu, s,  o);
        s2 += __shfl_xor_sync(0xffffffffu, s2, o);
    }
    if (lane == 0) {
        float mu  = s * (1.f / IND);
        float var = s2 * (1.f / IND) - mu * mu;
        g_mu[row] = mu;
        g_rs[row] = rsqrtf(var + 1e-5f);
    }
}

// ============================================================
// Kernel 2: SRWM sequential scan.
// One CTA per (b, head) pair (128 CTAs), 256 threads.
// Thread t owns row r = t>>2, columns [ (t&3)*16, +16 ) of Wy/Wq/Wk
// (register-resident). x, k, q-k, wb live in shared.
// ============================================================
__global__ __launch_bounds__(256, 1) void srwm_scan_kernel(
    const float* __restrict__ h,
    const float* __restrict__ Wy0, const float* __restrict__ Wq0,
    const float* __restrict__ Wk0, const float* __restrict__ wb0)
{
    const int pair = blockIdx.x;          // 0..127
    const int b  = pair >> 4;
    const int hd = pair & 15;
    const int tid  = threadIdx.x;
    const int r    = tid >> 2;            // row 0..63
    const int q4   = tid & 3;             // column quarter
    const int cb   = q4 * 16;             // column base
    const int lane = tid & 31;
    const int warp = tid >> 5;            // 0..7

    __shared__ float xs[64], ks[64], qmks[64];
    __shared__ float wb_s[4][64];         // [c][j]
    __shared__ float redq[8], redk[8], beta_s[4], dvb_s[4];

    // register-resident fast weights
    float wy[16], wq[16], wk[16];
    {
        const int base = hd * 4096 + r * 64 + cb;
        #pragma unroll
        for (int j = 0; j < 16; j += 4) {
            float4 ay = *(const float4*)(Wy0 + base + j);
            wy[j] = ay.x; wy[j+1] = ay.y; wy[j+2] = ay.z; wy[j+3] = ay.w;
            float4 aq = *(const float4*)(Wq0 + base + j);
            wq[j] = aq.x; wq[j+1] = aq.y; wq[j+2] = aq.z; wq[j+3] = aq.w;
            float4 ak = *(const float4*)(Wk0 + base + j);
            wk[j] = ak.x; wk[j+1] = ak.y; wk[j+2] = ak.z; wk[j+3] = ak.w;
        }
    }
    {   // wb: shape (hd, j=64, c=4) -> wb_s[c][j]
        int j = tid >> 2, c = tid & 3;
        wb_s[c][j] = wb0[hd * 256 + j * 4 + c];
    }

    const float* hp = h    + (size_t)b * IND + hd * 64;
    float*       yp = g_ys + (size_t)b * IND + hd * 64;
    const int    stride = BSZ * IND;

    for (int t = 0; t < SLEN; ++t) {
        if (tid < 64) xs[tid] = hp[(size_t)t * stride + tid];
        __syncthreads();   // S1: xs ready; prev-step wb_s update visible

        // ---- z = W x (pre-update weights) ----
        float zy = 0.f, zq = 0.f, zk = 0.f;
        #pragma unroll
        for (int j = 0; j < 16; j++) {
            float xv = xs[cb + j];
            zy = fmaf(wy[j], xv, zy);
            zq = fmaf(wq[j], xv, zq);
            zk = fmaf(wk[j], xv, zk);
        }
        zy += __shfl_xor_sync(0xffffffffu, zy, 1); zy += __shfl_xor_sync(0xffffffffu, zy, 2);
        zq += __shfl_xor_sync(0xffffffffu, zq, 1); zq += __shfl_xor_sync(0xffffffffu, zq, 2);
        zk += __shfl_xor_sync(0xffffffffu, zk, 1); zk += __shfl_xor_sync(0xffffffffu, zk, 2);

        // ---- softmax numerators + warp partial sums ----
        float eq = __expf(zq), ek = __expf(zk);
        float sq = eq, sk = ek;
        #pragma unroll
        for (int o = 16; o; o >>= 1) {
            sq += __shfl_xor_sync(0xffffffffu, sq, o);
            sk += __shfl_xor_sync(0xffffffffu, sk, o);
        }
        if (lane == 0) { redq[warp] = sq; redk[warp] = sk; }

        // ---- beta = sigmoid(wb^T x): warp c<4 computes beta[c] ----
        if (warp < 4) {
            float pb = fmaf(wb_s[warp][lane], xs[lane],
                            wb_s[warp][lane + 32] * xs[lane + 32]);
            #pragma unroll
            for (int o = 16; o; o >>= 1) pb += __shfl_xor_sync(0xffffffffu, pb, o);
            if (lane == 0) beta_s[warp] = 1.f / (1.f + __expf(-pb));
        }
        if (q4 == 0) yp[(size_t)t * stride + r] = zy;   // y output (pre-update Wy)
        __syncthreads();   // S2

        // ---- normalize softmax (warp sums counted each row 4x) ----
        float stq = 0.f, stk = 0.f;
        #pragma unroll
        for (int w = 0; w < 8; w++) { stq += redq[w]; stk += redk[w]; }
        float invq = 4.f / stq, invk = 4.f / stk;
        float qv = eq * invq, kv = ek * invk, mk = qv - kv;
        if (q4 == 0) { ks[r] = kv; qmks[r] = mk; }
        __syncthreads();   // S3

        // ---- dv = W (q - k) ----
        float dy = 0.f, dq = 0.f, dk = 0.f;
        #pragma unroll
        for (int j = 0; j < 16; j++) {
            float mv = qmks[cb + j];
            dy = fmaf(wy[j], mv, dy);
            dq = fmaf(wq[j], mv, dq);
            dk = fmaf(wk[j], mv, dk);
        }
        dy += __shfl_xor_sync(0xffffffffu, dy, 1); dy += __shfl_xor_sync(0xffffffffu, dy, 2);
        dq += __shfl_xor_sync(0xffffffffu, dq, 1); dq += __shfl_xor_sync(0xffffffffu, dq, 2);
        dk += __shfl_xor_sync(0xffffffffu, dk, 1); dk += __shfl_xor_sync(0xffffffffu, dk, 2);

        if (warp < 4) {  // dvb[c] = wb^T (q-k)
            float pd = fmaf(wb_s[warp][lane], qmks[lane],
                            wb_s[warp][lane + 32] * qmks[lane + 32]);
            #pragma unroll
            for (int o = 16; o; o >>= 1) pd += __shfl_xor_sync(0xffffffffu, pd, o);
            if (lane == 0) dvb_s[warp] = pd;
        }
        __syncthreads();   // S4: dvb ready; all wb_s/qmk reads done

        // ---- rank-1 updates: W += beta * dv k^T ----
        float a0 = beta_s[0] * dy, a1 = beta_s[1] * dq, a2 = beta_s[2] * dk;
        #pragma unroll
        for (int j = 0; j < 16; j++) {
            float kj = ks[cb + j];
            wy[j] = fmaf(a0, kj, wy[j]);
            wq[j] = fmaf(a1, kj, wq[j]);
            wk[j] = fmaf(a2, kj, wk[j]);
        }
        {   // wb += beta3 * k dvb^T (each thread one (c,j) element)
            int j = tid >> 2, c = tid & 3;
            wb_s[c][j] = fmaf(beta_s[3] * ks[j], dvb_s[c], wb_s[c][j]);
        }
        // next-iteration S1 orders wb_s write before its readers
    }
}

// ============================================================
// Kernel 3: out = LN(h) + ys @ out_w^T  (fused epilogue)
// 128x128 tile, BK=8, 256 threads, 8x8 per thread, f32x2 FMA.
// C[m,n] = sum_k ys[m,k] * out_w[n,k]
// ============================================================
__global__ __launch_bounds__(256, 1) void out_gemm_ln_kernel(
    const float* __restrict__ h, const float* __restrict__ W,
    const float* __restrict__ gamma, const float* __restrict__ lbeta,
    float* __restrict__ out)
{
    __shared__ float As[8][128];
    __shared__ float Bs[8][128];

    const int tid = threadIdx.x;
    const int tx = tid & 15, ty = tid >> 4;
    const int m0 = blockIdx.y * 128, n0 = blockIdx.x * 128;
    const int lrow = tid >> 1, lkg = tid & 1;

    unsigned long long acc[8][4];
    #pragma unroll
    for (int i = 0; i < 8; i++)
        #pragma unroll
        for (int j = 0; j < 4; j++) acc[i][j] = 0ull;

    const float* Ag = g_ys + (size_t)(m0 + lrow) * IND + lkg * 4;
    const float* Bg = W    + (size_t)(n0 + lrow) * IND + lkg * 4;

    for (int kt = 0; kt < IND / 8; ++kt) {
        float4 av = *(const float4*)(Ag + kt * 8);
        float4 bv = *(const float4*)(Bg + kt * 8);
        __syncthreads();
        As[lkg*4+0][lrow] = av.x; As[lkg*4+1][lrow] = av.y;
        As[lkg*4+2][lrow] = av.z; As[lkg*4+3][lrow] = av.w;
        Bs[lkg*4+0][lrow] = bv.x; Bs[lkg*4+1][lrow] = bv.y;
        Bs[lkg*4+2][lrow] = bv.z; Bs[lkg*4+3][lrow] = bv.w;
        __syncthreads();

        #pragma unroll
        for (int k = 0; k < 8; k++) {
            float4 a0 = *(const float4*)&As[k][ty * 4];
            float4 a1 = *(const float4*)&As[k][64 + ty * 4];
            unsigned long long b0 = *(const unsigned long long*)&Bs[k][tx * 4];
            unsigned long long b1 = *(const unsigned long long*)&Bs[k][tx * 4 + 2];
            unsigned long long b2 = *(const unsigned long long*)&Bs[k][64 + tx * 4];
            unsigned long long b3 = *(const unsigned long long*)&Bs[k][64 + tx * 4 + 2];
            float af[8] = {a0.x, a0.y, a0.z, a0.w, a1.x, a1.y, a1.z, a1.w};
            #pragma unroll
            for (int i = 0; i < 8; i++) {
                unsigned long long ad = pack2(af[i], af[i]);
                acc[i][0] = ffma2(ad, b0, acc[i][0]);
                acc[i][1] = ffma2(ad, b1, acc[i][1]);
                acc[i][2] = ffma2(ad, b2, acc[i][2]);
                acc[i][3] = ffma2(ad, b3, acc[i][3]);
            }
        }
    }

    // epilogue: out = acc + (h - mu) * rsig * gamma + beta
    #pragma unroll
    for (int i = 0; i < 8; i++) {
        int m = m0 + ((i < 4) ? (ty * 4 + i) : (64 + ty * 4 + i - 4));
        float muv = g_mu[m], rsv = g_rs[m];
        const float* hrow = h + (size_t)m * IND;
        float* orow = out + (size_t)m * IND;
        #pragma unroll
        for (int j = 0; j < 4; j++) {
            int n = n0 + ((j < 2) ? (tx * 4 + j * 2) : (64 + tx * 4 + (j - 2) * 2));
            float v0, v1;
            unpack2(acc[i][j], v0, v1);
            orow[n]     = v0 + (hrow[n]     - muv) * rsv * gamma[n]     + lbeta[n];
            orow[n + 1] = v1 + (hrow[n + 1] - muv) * rsv * gamma[n + 1] + lbeta[n + 1];
        }
    }
}

// ============================================================
extern "C" void kernel_launch(void* const* d_in, const int* in_sizes, int n_in,
                              void* d_out, int out_size) {
    const float* h   = (const float*)d_in[0];
    const float* Wy  = (const float*)d_in[1];
    const float* Wq  = (const float*)d_in[2];
    const float* Wk  = (const float*)d_in[3];
    const float* wb  = (const float*)d_in[4];
    const float* ow  = (const float*)d_in[5];
    const float* gam = (const float*)d_in[6];
    const float* bet = (const float*)d_in[7];
    float* out = (float*)d_out;

    ln_stats_kernel<<<ROWS / 8, 256>>>(h);
    srwm_scan_kernel<<<BSZ * NH, 256>>>(h, Wy, Wq, Wk, wb);
    out_gemm_ln_kernel<<<dim3(IND / 128, ROWS / 128), 256>>>(h, ow, gam, bet, out);
}

// round 2
// speedup vs baseline: 1.1129x; 1.1129x over previous
#include <cuda_runtime.h>

#define SLEN 256
#define BSZ 8
#define NH 16
#define DH 64
#define IND 1024
#define ROWS (SLEN*BSZ) /* 2048 */

typedef unsigned long long ull;

// ---- scratch (no allocs allowed -> device globals) ----
__device__ float g_ys[ROWS * IND];   // scan outputs, GEMM A operand (8 MB)
__device__ float g_mu[ROWS];
__device__ float g_rs[ROWS];

// ---- f32x2 helpers (sm_103a packed fp32 math, PTX-only) ----
__device__ __forceinline__ ull pack2(float lo, float hi) {
    ull r;
    asm("mov.b64 %0, {%1,%2};" : "=l"(r) : "f"(lo), "f"(hi));
    return r;
}
__device__ __forceinline__ void unpack2(ull v, float& lo, float& hi) {
    asm("mov.b64 {%0,%1}, %2;" : "=f"(lo), "=f"(hi) : "l"(v));
}
__device__ __forceinline__ ull ffma2(ull a, ull b, ull c) {
    ull d;
    asm("fma.rn.f32x2 %0, %1, %2, %3;" : "=l"(d) : "l"(a), "l"(b), "l"(c));
    return d;
}
__device__ __forceinline__ ull fmul2(ull a, ull b) {
    ull d;
    asm("mul.rn.f32x2 %0, %1, %2;" : "=l"(d) : "l"(a), "l"(b));
    return d;
}

// ============================================================
// Kernel 1: LayerNorm row stats (mu, 1/sigma) — one warp per row
// ============================================================
__global__ __launch_bounds__(256) void ln_stats_kernel(const float* __restrict__ h) {
    int row  = blockIdx.x * 8 + (threadIdx.x >> 5);
    int lane = threadIdx.x & 31;
    const float* p = h + (size_t)row * IND;
    float s = 0.f, s2 = 0.f;
    #pragma unroll 8
    for (int c = lane; c < IND; c += 32) {
        float v = p[c];
        s += v;
        s2 = fmaf(v, v, s2);
    }
    #pragma unroll
    for (int o = 16; o; o >>= 1) {
        s  += __shfl_xor_sync(0xffffffffu, s,  o);
        s2 += __shfl_xor_sync(0xffffffffu, s2, o);
    }
    if (lane == 0) {
        float mu  = s * (1.f / IND);
        float var = s2 * (1.f / IND) - mu * mu;
        g_mu[row] = mu;
        g_rs[row] = rsqrtf(var + 1e-5f);
    }
}

// ============================================================
// Kernel 2: SRWM sequential scan — 2 barriers/step, f32x2 math.
// One CTA per (b, head) pair (128 CTAs), 256 threads.
// Thread t owns row r=t>>2, cols [(t&3)*16, +16) of Wy/Wq/Wk as
// 8 packed f32x2 regs each. wb is warp-private to warps 0-3
// (warp c owns wb[:,c]; computes beta_c, dvb_c, and its update).
// ============================================================
__global__ __launch_bounds__(256, 1) void srwm_scan_kernel(
    const float* __restrict__ h,
    const float* __restrict__ Wy0, const float* __restrict__ Wq0,
    const float* __restrict__ Wk0, const float* __restrict__ wb0)
{
    const int pair = blockIdx.x;          // 0..127
    const int b  = pair >> 4;
    const int hd = pair & 15;
    const int tid  = threadIdx.x;
    const int r    = tid >> 2;            // row 0..63
    const int q4   = tid & 3;             // column quarter
    const int cb   = q4 * 16;             // column base
    const int lane = tid & 31;
    const int warp = tid >> 5;            // 0..7

    __shared__ __align__(16) float xs[64];
    __shared__ __align__(16) float eqs[64], eks[64];
    __shared__ __align__(16) float redq[8], redk[8];
    __shared__ __align__(16) float beta_s[4];

    // register-resident fast weights as packed f32x2 pairs
    ull wy2[8], wq2[8], wk2[8];
    {
        const int base = hd * 4096 + r * 64 + cb;   // 16B-aligned (cb mult of 16)
        const ulonglong2* py = (const ulonglong2*)(Wy0 + base);
        const ulonglong2* pq = (const ulonglong2*)(Wq0 + base);
        const ulonglong2* pk = (const ulonglong2*)(Wk0 + base);
        #pragma unroll
        for (int j = 0; j < 4; j++) {
            ulonglong2 vy = py[j]; wy2[2*j] = vy.x; wy2[2*j+1] = vy.y;
            ulonglong2 vq = pq[j]; wq2[2*j] = vq.x; wq2[2*j+1] = vq.y;
            ulonglong2 vk = pk[j]; wk2[2*j] = vk.x; wk2[2*j+1] = vk.y;
        }
    }
    // wb: global layout (hd, j=64, c=4). Warp c owns column c:
    // lane holds wb[lane][c] and wb[lane+32][c].
    float wbl = 0.f, wbh = 0.f;
    if (warp < 4) {
        wbl = wb0[hd * 256 + lane * 4 + warp];
        wbh = wb0[hd * 256 + (lane + 32) * 4 + warp];
    }

    const float* hp = h    + (size_t)b * IND + hd * 64;
    float*       yp = g_ys + (size_t)b * IND + hd * 64;
    const int    stride = BSZ * IND;

    if (tid < 64) xs[tid] = hp[tid];
    __syncthreads();

    for (int t = 0; t < SLEN; ++t) {
        // ================= Phase A =================
        // z = W x (pre-update weights), packed
        ull ay = 0ull, aq = 0ull, ak = 0ull;
        #pragma unroll
        for (int j = 0; j < 8; j++) {
            ull x2 = *(const ull*)&xs[cb + 2*j];
            ay = ffma2(wy2[j], x2, ay);
            aq = ffma2(wq2[j], x2, aq);
            ak = ffma2(wk2[j], x2, ak);
        }
        float zy, zq, zk, hi_;
        unpack2(ay, zy, hi_); zy += hi_;
        unpack2(aq, zq, hi_); zq += hi_;
        unpack2(ak, zk, hi_); zk += hi_;
        zy += __shfl_xor_sync(0xffffffffu, zy, 1); zy += __shfl_xor_sync(0xffffffffu, zy, 2);
        zq += __shfl_xor_sync(0xffffffffu, zq, 1); zq += __shfl_xor_sync(0xffffffffu, zq, 2);
        zk += __shfl_xor_sync(0xffffffffu, zk, 1); zk += __shfl_xor_sync(0xffffffffu, zk, 2);

        float eq = __expf(zq), ek = __expf(zk);
        // warp softmax partials: values uniform within groups of 4, so
        // 3 xor levels (4,8,16) give the true 8-row sum on every lane.
        float sq = eq, sk = ek;
        sq += __shfl_xor_sync(0xffffffffu, sq, 4);  sk += __shfl_xor_sync(0xffffffffu, sk, 4);
        sq += __shfl_xor_sync(0xffffffffu, sq, 8);  sk += __shfl_xor_sync(0xffffffffu, sk, 8);
        sq += __shfl_xor_sync(0xffffffffu, sq, 16); sk += __shfl_xor_sync(0xffffffffu, sk, 16);
        if (lane == 0) { redq[warp] = sq; redk[warp] = sk; }
        if (q4 == 0) {
            eqs[r] = eq; eks[r] = ek;
            yp[(size_t)t * stride + r] = zy;      // y output (pre-update Wy)
        }
        // beta_c = sigmoid(wb[:,c]^T x) — warp c, private wb regs
        if (warp < 4) {
            float pb = fmaf(wbl, xs[lane], wbh * xs[lane + 32]);
            #pragma unroll
            for (int o = 16; o; o >>= 1) pb += __shfl_xor_sync(0xffffffffu, pb, o);
            if (lane == 0) beta_s[warp] = 1.f / (1.f + __expf(-pb));
        }
        __syncthreads();   // S2: eqs/eks/redq/redk/beta_s published; xs reads done

        // prefetch next x (old xs fully consumed before S2)
        if (tid < 64 && t + 1 < SLEN) xs[tid] = hp[(size_t)(t + 1) * stride + tid];

        // ================= Phase B =================
        float stq = ((redq[0]+redq[1])+(redq[2]+redq[3]))+((redq[4]+redq[5])+(redq[6]+redq[7]));
        float stk = ((redk[0]+redk[1])+(redk[2]+redk[3]))+((redk[4]+redk[5])+(redk[6]+redk[7]));
        float invq = __fdividef(1.f, stq);
        float invk = __fdividef(1.f, stk);
        ull invq2  = pack2(invq, invq);
        ull invk2  = pack2(invk, invk);
        ull ninvk2 = pack2(-invk, -invk);

        // dv = W (q - k), with qmk formed locally from numerators
        ull dy2 = 0ull, dq2 = 0ull, dk2 = 0ull;
        ull ek2[8];
        #pragma unroll
        for (int j = 0; j < 8; j++) {
            ull eq2 = *(const ull*)&eqs[cb + 2*j];
            ek2[j]  = *(const ull*)&eks[cb + 2*j];
            ull mk2 = ffma2(ek2[j], ninvk2, fmul2(eq2, invq2));
            dy2 = ffma2(wy2[j], mk2, dy2);
            dq2 = ffma2(wq2[j], mk2, dq2);
            dk2 = ffma2(wk2[j], mk2, dk2);
        }
        float dy, dq, dk;
        unpack2(dy2, dy, hi_); dy += hi_;
        unpack2(dq2, dq, hi_); dq += hi_;
        unpack2(dk2, dk, hi_); dk += hi_;
        dy += __shfl_xor_sync(0xffffffffu, dy, 1); dy += __shfl_xor_sync(0xffffffffu, dy, 2);
        dq += __shfl_xor_sync(0xffffffffu, dq, 1); dq += __shfl_xor_sync(0xffffffffu, dq, 2);
        dk += __shfl_xor_sync(0xffffffffu, dk, 1); dk += __shfl_xor_sync(0xffffffffu, dk, 2);

        // rank-1 updates: W += beta * dv k^T (all local after beta_s read)
        float a0 = beta_s[0] * dy, a1 = beta_s[1] * dq, a2 = beta_s[2] * dk;
        ull a02 = pack2(a0, a0), a12 = pack2(a1, a1), a22 = pack2(a2, a2);
        #pragma unroll
        for (int j = 0; j < 8; j++) {
            ull kv2 = fmul2(ek2[j], invk2);
            wy2[j] = ffma2(a02, kv2, wy2[j]);
            wq2[j] = ffma2(a12, kv2, wq2[j]);
            wk2[j] = ffma2(a22, kv2, wk2[j]);
        }
        // wb update: warp c computes dvb_c and updates its private column
        if (warp < 4) {
            float ql = eqs[lane]      * invq - eks[lane]      * invk;
            float qh = eqs[lane + 32] * invq - eks[lane + 32] * invk;
            float pd = fmaf(wbl, ql, wbh * qh);
            #pragma unroll
            for (int o = 16; o; o >>= 1) pd += __shfl_xor_sync(0xffffffffu, pd, o);
            float b3  = beta_s[3];
            float kvl = eks[lane] * invk, kvh = eks[lane + 32] * invk;
            wbl = fmaf(b3 * kvl, pd, wbl);
            wbh = fmaf(b3 * kvh, pd, wbh);
        }
        __syncthreads();   // S4: phase-B smem reads done; next xs visible
    }
}

// ============================================================
// Kernel 3: out = LN(h) + ys @ out_w^T  (fused epilogue)
// 128x128 tile, BK=8, 256 threads, 8x8 per thread, f32x2 FMA.
// Double-buffered smem (1 barrier/kt), A staged as dup'd pairs.
// C[m,n] = sum_k ys[m,k] * out_w[n,k]
// ============================================================
__global__ __launch_bounds__(256, 1) void out_gemm_ln_kernel(
    const float* __restrict__ h, const float* __restrict__ W,
    const float* __restrict__ gamma, const float* __restrict__ lbeta,
    float* __restrict__ out)
{
    __shared__ __align__(16) ull   Asd[2][8][128];   // dup'd f32x2 pairs, 16KB
    __shared__ __align__(16) float Bs [2][8][128];   // 8KB

    const int tid = threadIdx.x;
    const int tx = tid & 15, ty = tid >> 4;
    const int m0 = blockIdx.y * 128, n0 = blockIdx.x * 128;
    const int lrow = tid >> 1, lkg = tid & 1;

    ull acc[8][4];
    #pragma unroll
    for (int i = 0; i < 8; i++)
        #pragma unroll
        for (int j = 0; j < 4; j++) acc[i][j] = 0ull;

    const float* Ag = g_ys + (size_t)(m0 + lrow) * IND + lkg * 4;
    const float* Bg = W    + (size_t)(n0 + lrow) * IND + lkg * 4;

    float4 av = *(const float4*)(Ag);
    float4 bv = *(const float4*)(Bg);

    for (int kt = 0; kt < IND / 8; ++kt) {
        const int buf = kt & 1;
        Asd[buf][lkg*4+0][lrow] = pack2(av.x, av.x);
        Asd[buf][lkg*4+1][lrow] = pack2(av.y, av.y);
        Asd[buf][lkg*4+2][lrow] = pack2(av.z, av.z);
        Asd[buf][lkg*4+3][lrow] = pack2(av.w, av.w);
        Bs[buf][lkg*4+0][lrow] = bv.x; Bs[buf][lkg*4+1][lrow] = bv.y;
        Bs[buf][lkg*4+2][lrow] = bv.z; Bs[buf][lkg*4+3][lrow] = bv.w;
        __syncthreads();
        if (kt + 1 < IND / 8) {
            av = *(const float4*)(Ag + (kt + 1) * 8);
            bv = *(const float4*)(Bg + (kt + 1) * 8);
        }
        #pragma unroll
        for (int k = 0; k < 8; k++) {
            ulonglong2 A0 = *(const ulonglong2*)&Asd[buf][k][ty * 4];
            ulonglong2 A1 = *(const ulonglong2*)&Asd[buf][k][ty * 4 + 2];
            ulonglong2 A2 = *(const ulonglong2*)&Asd[buf][k][64 + ty * 4];
            ulonglong2 A3 = *(const ulonglong2*)&Asd[buf][k][64 + ty * 4 + 2];
            ulonglong2 B0 = *(const ulonglong2*)&Bs[buf][k][tx * 4];
            ulonglong2 B1 = *(const ulonglong2*)&Bs[buf][k][64 + tx * 4];
            ull ad[8] = {A0.x, A0.y, A1.x, A1.y, A2.x, A2.y, A3.x, A3.y};
            #pragma unroll
            for (int i = 0; i < 8; i++) {
                acc[i][0] = ffma2(ad[i], B0.x, acc[i][0]);
                acc[i][1] = ffma2(ad[i], B0.y, acc[i][1]);
                acc[i][2] = ffma2(ad[i], B1.x, acc[i][2]);
                acc[i][3] = ffma2(ad[i], B1.y, acc[i][3]);
            }
        }
        // next iter stores to buf^1: all threads finished reading buf^1
        // (kt-1 compute) before this iteration's barrier — safe.
    }

    // epilogue: out = acc + (h - mu) * rsig * gamma + beta
    #pragma unroll
    for (int i = 0; i < 8; i++) {
        int m = m0 + ((i < 4) ? (ty * 4 + i) : (64 + ty * 4 + i - 4));
        float muv = g_mu[m], rsv = g_rs[m];
        const float* hrow = h + (size_t)m * IND;
        float* orow = out + (size_t)m * IND;
        #pragma unroll
        for (int j = 0; j < 4; j++) {
            int n = n0 + ((j < 2) ? (tx * 4 + j * 2) : (64 + tx * 4 + (j - 2) * 2));
            float v0, v1;
            unpack2(acc[i][j], v0, v1);
            orow[n]     = v0 + (hrow[n]     - muv) * rsv * gamma[n]     + lbeta[n];
            orow[n + 1] = v1 + (hrow[n + 1] - muv) * rsv * gamma[n + 1] + lbeta[n + 1];
        }
    }
}

// ============================================================
extern "C" void kernel_launch(void* const* d_in, const int* in_sizes, int n_in,
                              void* d_out, int out_size) {
    const float* h   = (const float*)d_in[0];
    const float* Wy  = (const float*)d_in[1];
    const float* Wq  = (const float*)d_in[2];
    const float* Wk  = (const float*)d_in[3];
    const float* wb  = (const float*)d_in[4];
    const float* ow  = (const float*)d_in[5];
    const float* gam = (const float*)d_in[6];
    const float* bet = (const float*)d_in[7];
    float* out = (float*)d_out;

    ln_stats_kernel<<<ROWS / 8, 256>>>(h);
    srwm_scan_kernel<<<BSZ * NH, 256>>>(h, Wy, Wq, Wk, wb);
    out_gemm_ln_kernel<<<dim3(IND / 128, ROWS / 128), 256>>>(h, ow, gam, bet, out);
}

// round 3
// speedup vs baseline: 1.1789x; 1.0593x over previous
#include <cuda_runtime.h>

#define SLEN 256
#define BSZ 8
#define NH 16
#define DH 64
#define IND 1024
#define ROWS (SLEN*BSZ) /* 2048 */

typedef unsigned long long ull;

// ---- scratch (no allocs allowed -> device globals) ----
__device__ float g_ys[ROWS * IND];   // scan outputs, GEMM A operand (8 MB)
__device__ float g_mu[ROWS];
__device__ float g_rs[ROWS];

// ---- f32x2 helpers (sm_103a packed fp32 math, PTX-only) ----
__device__ __forceinline__ ull pack2(float lo, float hi) {
    ull r;
    asm("mov.b64 %0, {%1,%2};" : "=l"(r) : "f"(lo), "f"(hi));
    return r;
}
__device__ __forceinline__ void unpack2(ull v, float& lo, float& hi) {
    asm("mov.b64 {%0,%1}, %2;" : "=f"(lo), "=f"(hi) : "l"(v));
}
__device__ __forceinline__ ull ffma2(ull a, ull b, ull c) {
    ull d;
    asm("fma.rn.f32x2 %0, %1, %2, %3;" : "=l"(d) : "l"(a), "l"(b), "l"(c));
    return d;
}
__device__ __forceinline__ ull fmul2(ull a, ull b) {
    ull d;
    asm("mul.rn.f32x2 %0, %1, %2;" : "=l"(d) : "l"(a), "l"(b));
    return d;
}
__device__ __forceinline__ ull fadd2(ull a, ull b) {
    ull d;
    asm("add.rn.f32x2 %0, %1, %2;" : "=l"(d) : "l"(a), "l"(b));
    return d;
}

// ============================================================
// Kernel 1: LN row stats (fused prologue) + SRWM sequential scan.
// One CTA per (b, head) pair (128 CTAs), 256 threads.
// Single __syncthreads per scan step: phase-A smem outputs are
// double-buffered by step parity; phase B writes only registers.
// Thread t owns row r=t>>2, cols [(t&3)*16,+16) of Wy/Wq/Wk as
// 8 packed f32x2 regs each. wb[:,c] is private to warp c (c<4).
// ============================================================
__global__ __launch_bounds__(256, 1) void srwm_scan_kernel(
    const float* __restrict__ h,
    const float* __restrict__ Wy0, const float* __restrict__ Wq0,
    const float* __restrict__ Wk0, const float* __restrict__ wb0)
{
    const int pair = blockIdx.x;          // 0..127
    const int b  = pair >> 4;
    const int hd = pair & 15;
    const int tid  = threadIdx.x;
    const int r    = tid >> 2;            // row 0..63
    const int q4   = tid & 3;             // column quarter
    const int cb   = q4 * 16;             // column base
    const int lane = tid & 31;
    const int warp = tid >> 5;            // 0..7

    // ---------- fused LayerNorm stats: 16 rows per CTA ----------
    {
        #pragma unroll
        for (int rr = 0; rr < 2; rr++) {
            int row = pair * 16 + warp * 2 + rr;
            const float* p = h + (size_t)row * IND + lane * 4;
            float s = 0.f, s2 = 0.f;
            #pragma unroll
            for (int i = 0; i < 8; i++) {
                float4 v = *(const float4*)(p + i * 128);
                s += (v.x + v.y) + (v.z + v.w);
                s2 = fmaf(v.x, v.x, s2); s2 = fmaf(v.y, v.y, s2);
                s2 = fmaf(v.z, v.z, s2); s2 = fmaf(v.w, v.w, s2);
            }
            #pragma unroll
            for (int o = 16; o; o >>= 1) {
                s  += __shfl_xor_sync(0xffffffffu, s,  o);
                s2 += __shfl_xor_sync(0xffffffffu, s2, o);
            }
            if (lane == 0) {
                float mu  = s * (1.f / IND);
                float var = s2 * (1.f / IND) - mu * mu;
                g_mu[row] = mu;
                g_rs[row] = rsqrtf(var + 1e-5f);
            }
        }
    }

    __shared__ __align__(16) float xs[2][64];
    __shared__ __align__(16) float eqs[2][64], eks[2][64];
    __shared__ __align__(16) float redq[2][8], redk[2][8];
    __shared__ __align__(16) float beta_s[2][4];

    // register-resident fast weights as packed f32x2 pairs
    ull wy2[8], wq2[8], wk2[8];
    {
        const int base = hd * 4096 + r * 64 + cb;   // 16B-aligned
        const ulonglong2* py = (const ulonglong2*)(Wy0 + base);
        const ulonglong2* pq = (const ulonglong2*)(Wq0 + base);
        const ulonglong2* pk = (const ulonglong2*)(Wk0 + base);
        #pragma unroll
        for (int j = 0; j < 4; j++) {
            ulonglong2 vy = py[j]; wy2[2*j] = vy.x; wy2[2*j+1] = vy.y;
            ulonglong2 vq = pq[j]; wq2[2*j] = vq.x; wq2[2*j+1] = vq.y;
            ulonglong2 vk = pk[j]; wk2[2*j] = vk.x; wk2[2*j+1] = vk.y;
        }
    }
    // wb: global layout (hd, j=64, c=4). Warp c owns column c.
    float wbl = 0.f, wbh = 0.f;
    if (warp < 4) {
        wbl = wb0[hd * 256 + lane * 4 + warp];
        wbh = wb0[hd * 256 + (lane + 32) * 4 + warp];
    }

    const float* hp = h    + (size_t)b * IND + hd * 64;
    float*       yp = g_ys + (size_t)b * IND + hd * 64;
    const int    stride = BSZ * IND;

    // preload x[0] into bank 0 (warps 4,5)
    if (tid >= 128 && tid < 192) xs[0][tid - 128] = hp[tid - 128];
    __syncthreads();

    for (int t = 0; t < SLEN; ++t) {
        const int p  = t & 1;
        const int pn = p ^ 1;

        // ---- prefetch x[t+1] (warps 4,5): issue LDG first ----
        float nx = 0.f;
        const bool pf = (tid >= 128 && tid < 192) && (t + 1 < SLEN);
        if (pf) nx = __ldg(hp + (size_t)(t + 1) * stride + (tid - 128));

        // ================= Phase A (reads xs[p]) =================
        ull ayA = 0ull, ayB = 0ull, aqA = 0ull, aqB = 0ull, akA = 0ull, akB = 0ull;
        #pragma unroll
        for (int j = 0; j < 4; j++) {
            ull x2a = *(const ull*)&xs[p][cb + 2*j];
            ull x2b = *(const ull*)&xs[p][cb + 8 + 2*j];
            ayA = ffma2(wy2[j], x2a, ayA);  ayB = ffma2(wy2[j+4], x2b, ayB);
            aqA = ffma2(wq2[j], x2a, aqA);  aqB = ffma2(wq2[j+4], x2b, aqB);
            akA = ffma2(wk2[j], x2a, akA);  akB = ffma2(wk2[j+4], x2b, akB);
        }
        ull ay = fadd2(ayA, ayB), aq = fadd2(aqA, aqB), ak = fadd2(akA, akB);
        float zy, zq, zk, hi_;
        unpack2(ay, zy, hi_); zy += hi_;
        unpack2(aq, zq, hi_); zq += hi_;
        unpack2(ak, zk, hi_); zk += hi_;
        zy += __shfl_xor_sync(0xffffffffu, zy, 1); zy += __shfl_xor_sync(0xffffffffu, zy, 2);
        zq += __shfl_xor_sync(0xffffffffu, zq, 1); zq += __shfl_xor_sync(0xffffffffu, zq, 2);
        zk += __shfl_xor_sync(0xffffffffu, zk, 1); zk += __shfl_xor_sync(0xffffffffu, zk, 2);

        float eq = __expf(zq), ek = __expf(zk);
        // quad-uniform values: 3 xor levels give exact 8-row warp sum
        float sq = eq, sk = ek;
        sq += __shfl_xor_sync(0xffffffffu, sq, 4);  sk += __shfl_xor_sync(0xffffffffu, sk, 4);
        sq += __shfl_xor_sync(0xffffffffu, sq, 8);  sk += __shfl_xor_sync(0xffffffffu, sk, 8);
        sq += __shfl_xor_sync(0xffffffffu, sq, 16); sk += __shfl_xor_sync(0xffffffffu, sk, 16);
        if (lane == 0) { redq[p][warp] = sq; redk[p][warp] = sk; }
        if (q4 == 0) {
            eqs[p][r] = eq; eks[p][r] = ek;
            yp[(size_t)t * stride + r] = zy;      // y output (pre-update Wy)
        }
        // beta_c = sigmoid(wb[:,c]^T x) — warp c, private wb regs
        if (warp < 4) {
            float pb = fmaf(wbl, xs[p][lane], wbh * xs[p][lane + 32]);
            #pragma unroll
            for (int o = 16; o; o >>= 1) pb += __shfl_xor_sync(0xffffffffu, pb, o);
            if (lane == 0) beta_s[p][warp] = 1.f / (1.f + __expf(-pb));
        }
        if (pf) xs[pn][tid - 128] = nx;           // publish x[t+1]
        __syncthreads();   // single barrier per step

        // ============ Phase B (reads bank p, writes regs only) ============
        float stq = ((redq[p][0]+redq[p][1])+(redq[p][2]+redq[p][3]))
                  + ((redq[p][4]+redq[p][5])+(redq[p][6]+redq[p][7]));
        float stk = ((redk[p][0]+redk[p][1])+(redk[p][2]+redk[p][3]))
                  + ((redk[p][4]+redk[p][5])+(redk[p][6]+redk[p][7]));
        float invq = __fdividef(1.f, stq);
        float invk = __fdividef(1.f, stk);
        ull invq2  = pack2(invq, invq);
        ull invk2  = pack2(invk, invk);
        ull ninvk2 = pack2(-invk, -invk);

        // dv = W (q - k), qmk formed locally from numerators
        ull dyA = 0ull, dyB = 0ull, dqA = 0ull, dqB = 0ull, dkA = 0ull, dkB = 0ull;
        ull ek2[8];
        #pragma unroll
        for (int j = 0; j < 4; j++) {
            ull eqa = *(const ull*)&eqs[p][cb + 2*j];
            ull eqb = *(const ull*)&eqs[p][cb + 8 + 2*j];
            ek2[j]   = *(const ull*)&eks[p][cb + 2*j];
            ek2[j+4] = *(const ull*)&eks[p][cb + 8 + 2*j];
            ull mka = ffma2(ek2[j],   ninvk2, fmul2(eqa, invq2));
            ull mkb = ffma2(ek2[j+4], ninvk2, fmul2(eqb, invq2));
            dyA = ffma2(wy2[j], mka, dyA);  dyB = ffma2(wy2[j+4], mkb, dyB);
            dqA = ffma2(wq2[j], mka, dqA);  dqB = ffma2(wq2[j+4], mkb, dqB);
            dkA = ffma2(wk2[j], mka, dkA);  dkB = ffma2(wk2[j+4], mkb, dkB);
        }
        ull dy2 = fadd2(dyA, dyB), dq2 = fadd2(dqA, dqB), dk2 = fadd2(dkA, dkB);
        float dy, dq, dk;
        unpack2(dy2, dy, hi_); dy += hi_;
        unpack2(dq2, dq, hi_); dq += hi_;
        unpack2(dk2, dk, hi_); dk += hi_;
        dy += __shfl_xor_sync(0xffffffffu, dy, 1); dy += __shfl_xor_sync(0xffffffffu, dy, 2);
        dq += __shfl_xor_sync(0xffffffffu, dq, 1); dq += __shfl_xor_sync(0xffffffffu, dq, 2);
        dk += __shfl_xor_sync(0xffffffffu, dk, 1); dk += __shfl_xor_sync(0xffffffffu, dk, 2);

        // rank-1 updates: W += beta * dv k^T (registers only)
        float a0 = beta_s[p][0] * dy, a1 = beta_s[p][1] * dq, a2 = beta_s[p][2] * dk;
        ull a02 = pack2(a0, a0), a12 = pack2(a1, a1), a22 = pack2(a2, a2);
        #pragma unroll
        for (int j = 0; j < 8; j++) {
            ull kv2 = fmul2(ek2[j], invk2);
            wy2[j] = ffma2(a02, kv2, wy2[j]);
            wq2[j] = ffma2(a12, kv2, wq2[j]);
            wk2[j] = ffma2(a22, kv2, wk2[j]);
        }
        // wb update: warp c computes dvb_c, updates its private column
        if (warp < 4) {
            float ql = eqs[p][lane]      * invq - eks[p][lane]      * invk;
            float qh = eqs[p][lane + 32] * invq - eks[p][lane + 32] * invk;
            float pd = fmaf(wbl, ql, wbh * qh);
            #pragma unroll
            for (int o = 16; o; o >>= 1) pd += __shfl_xor_sync(0xffffffffu, pd, o);
            float b3  = beta_s[p][3];
            float kvl = eks[p][lane] * invk, kvh = eks[p][lane + 32] * invk;
            wbl = fmaf(b3 * kvl, pd, wbl);
            wbh = fmaf(b3 * kvh, pd, wbh);
        }
        // no trailing barrier: next phase A uses xs[pn] (covered by the
        // barrier above) and writes smem bank pn only.
    }
}

// ============================================================
// Kernel 2: out = LN(h) + ys @ out_w^T  (fused epilogue)
// 128x128 tile, BK=8, 256 threads, 8x8 per thread, f32x2 FMA.
// Scalar smem staging (64B/thread/k), double-buffered, 1 bar/kt.
// C[m,n] = sum_k ys[m,k] * out_w[n,k]
// ============================================================
__global__ __launch_bounds__(256, 1) void out_gemm_ln_kernel(
    const float* __restrict__ h, const float* __restrict__ W,
    const float* __restrict__ gamma, const float* __restrict__ lbeta,
    float* __restrict__ out)
{
    __shared__ __align__(16) float As[2][8][128];
    __shared__ __align__(16) float Bs[2][8][128];

    const int tid = threadIdx.x;
    const int tx = tid & 15, ty = tid >> 4;
    const int m0 = blockIdx.y * 128, n0 = blockIdx.x * 128;
    const int lrow = tid >> 1, lkg = tid & 1;

    ull acc[8][4];
    #pragma unroll
    for (int i = 0; i < 8; i++)
        #pragma unroll
        for (int j = 0; j < 4; j++) acc[i][j] = 0ull;

    const float* Ag = g_ys + (size_t)(m0 + lrow) * IND + lkg * 4;
    const float* Bg = W    + (size_t)(n0 + lrow) * IND + lkg * 4;

    float4 av = *(const float4*)(Ag);
    float4 bv = *(const float4*)(Bg);

    for (int kt = 0; kt < IND / 8; ++kt) {
        const int buf = kt & 1;
        As[buf][lkg*4+0][lrow] = av.x; As[buf][lkg*4+1][lrow] = av.y;
        As[buf][lkg*4+2][lrow] = av.z; As[buf][lkg*4+3][lrow] = av.w;
        Bs[buf][lkg*4+0][lrow] = bv.x; Bs[buf][lkg*4+1][lrow] = bv.y;
        Bs[buf][lkg*4+2][lrow] = bv.z; Bs[buf][lkg*4+3][lrow] = bv.w;
        __syncthreads();
        if (kt + 1 < IND / 8) {
            av = *(const float4*)(Ag + (kt + 1) * 8);
            bv = *(const float4*)(Bg + (kt + 1) * 8);
        }
        #pragma unroll
        for (int k = 0; k < 8; k++) {
            float4 a0 = *(const float4*)&As[buf][k][ty * 4];
            float4 a1 = *(const float4*)&As[buf][k][64 + ty * 4];
            ulonglong2 B0 = *(const ulonglong2*)&Bs[buf][k][tx * 4];
            ulonglong2 B1 = *(const ulonglong2*)&Bs[buf][k][64 + tx * 4];
            float af[8] = {a0.x, a0.y, a0.z, a0.w, a1.x, a1.y, a1.z, a1.w};
            #pragma unroll
            for (int i = 0; i < 8; i++) {
                ull ad = pack2(af[i], af[i]);
                acc[i][0] = ffma2(ad, B0.x, acc[i][0]);
                acc[i][1] = ffma2(ad, B0.y, acc[i][1]);
                acc[i][2] = ffma2(ad, B1.x, acc[i][2]);
                acc[i][3] = ffma2(ad, B1.y, acc[i][3]);
            }
        }
    }

    // epilogue: out = acc + (h - mu) * rsig * gamma + beta
    #pragma unroll
    for (int i = 0; i < 8; i++) {
        int m = m0 + ((i < 4) ? (ty * 4 + i) : (64 + ty * 4 + i - 4));
        float muv = g_mu[m], rsv = g_rs[m];
        const float* hrow = h + (size_t)m * IND;
        float* orow = out + (size_t)m * IND;
        #pragma unroll
        for (int j = 0; j < 4; j++) {
            int n = n0 + ((j < 2) ? (tx * 4 + j * 2) : (64 + tx * 4 + (j - 2) * 2));
            float v0, v1;
            unpack2(acc[i][j], v0, v1);
            orow[n]     = v0 + (hrow[n]     - muv) * rsv * gamma[n]     + lbeta[n];
            orow[n + 1] = v1 + (hrow[n + 1] - muv) * rsv * gamma[n + 1] + lbeta[n + 1];
        }
    }
}

// ============================================================
extern "C" void kernel_launch(void* const* d_in, const int* in_sizes, int n_in,
                              void* d_out, int out_size) {
    const float* h   = (const float*)d_in[0];
    const float* Wy  = (const float*)d_in[1];
    const float* Wq  = (const float*)d_in[2];
    const float* Wk  = (const float*)d_in[3];
    const float* wb  = (const float*)d_in[4];
    const float* ow  = (const float*)d_in[5];
    const float* gam = (const float*)d_in[6];
    const float* bet = (const float*)d_in[7];
    float* out = (float*)d_out;

    srwm_scan_kernel<<<BSZ * NH, 256>>>(h, Wy, Wq, Wk, wb);
    out_gemm_ln_kernel<<<dim3(IND / 128, ROWS / 128), 256>>>(h, ow, gam, bet, out);
}

// round 5
// speedup vs baseline: 1.5275x; 1.2957x over previous
#include <cuda_runtime.h>

#define SLEN 256
#define BSZ 8
#define NH 16
#define DH 64
#define IND 1024
#define ROWS (SLEN*BSZ) /* 2048 */

typedef unsigned long long ull;

// ---- scratch (no allocs allowed -> device globals) ----
__device__ float g_ys[ROWS * IND];   // scan outputs, GEMM A operand (8 MB)
__device__ float g_mu[ROWS];
__device__ float g_rs[ROWS];

// ---- f32x2 helpers (sm_103a packed fp32 math, PTX-only) ----
__device__ __forceinline__ ull pack2(float lo, float hi) {
    ull r;
    asm("mov.b64 %0, {%1,%2};" : "=l"(r) : "f"(lo), "f"(hi));
    return r;
}
__device__ __forceinline__ void unpack2(ull v, float& lo, float& hi) {
    asm("mov.b64 {%0,%1}, %2;" : "=f"(lo), "=f"(hi) : "l"(v));
}
__device__ __forceinline__ ull ffma2(ull a, ull b, ull c) {
    ull d;
    asm("fma.rn.f32x2 %0, %1, %2, %3;" : "=l"(d) : "l"(a), "l"(b), "l"(c));
    return d;
}
__device__ __forceinline__ ull fmul2(ull a, ull b) {
    ull d;
    asm("mul.rn.f32x2 %0, %1, %2;" : "=l"(d) : "l"(a), "l"(b));
    return d;
}
__device__ __forceinline__ ull fadd2(ull a, ull b) {
    ull d;
    asm("add.rn.f32x2 %0, %1, %2;" : "=l"(d) : "l"(a), "l"(b));
    return d;
}
// full warp sum (per-lane distinct values): 5 shfls
__device__ __forceinline__ float warp_sum(float v) {
    #pragma unroll
    for (int o = 16; o; o >>= 1) v += __shfl_xor_sync(0xffffffffu, v, o);
    return v;
}
// warp sum when values are uniform within lane pairs (lane, lane^1):
// xor offsets 2,4,8,16 hit each of the 16 pairs exactly once -> 4 shfls
__device__ __forceinline__ float warp_sum_pairs(float v) {
    v += __shfl_xor_sync(0xffffffffu, v, 2);
    v += __shfl_xor_sync(0xffffffffu, v, 4);
    v += __shfl_xor_sync(0xffffffffu, v, 8);
    v += __shfl_xor_sync(0xffffffffu, v, 16);
    return v;
}

// ============================================================
// Kernel 1: LN row stats (fused prologue) + SRWM sequential scan.
// One CTA per (b, head) pair (128 CTAs), 128 threads (4 warps).
// Thread t owns row r=t>>1, cols [(t&1)*32,+32) of Wy/Wq/Wk as
// 16 packed f32x2 regs each. Warp c (0..3) owns wb[:,c]/beta_c.
// Single barrier per step; phase-A smem outputs double-buffered
// by step parity; phase B writes registers only. x prefetched
// two steps ahead (LDG in phase B, STS in next phase A).
// ============================================================
__global__ __launch_bounds__(128, 1) void srwm_scan_kernel(
    const float* __restrict__ h,
    const float* __restrict__ Wy0, const float* __restrict__ Wq0,
    const float* __restrict__ Wk0, const float* __restrict__ wb0)
{
    const int pair = blockIdx.x;          // 0..127
    const int b  = pair >> 4;
    const int hd = pair & 15;
    const int tid  = threadIdx.x;
    const int r    = tid >> 1;            // row 0..63
    const int hf   = tid & 1;             // column half
    const int cb   = hf * 32;             // column base
    const int lane = tid & 31;
    const int warp = tid >> 5;            // 0..3

    // ---------- fused LayerNorm stats: 16 rows per CTA ----------
    {
        #pragma unroll
        for (int rr = 0; rr < 4; rr++) {
            int row = pair * 16 + warp * 4 + rr;
            const float* p = h + (size_t)row * IND + lane * 4;
            float s = 0.f, s2 = 0.f;
            #pragma unroll
            for (int i = 0; i < 8; i++) {
                float4 v = *(const float4*)(p + i * 128);
                s += (v.x + v.y) + (v.z + v.w);
                s2 = fmaf(v.x, v.x, s2); s2 = fmaf(v.y, v.y, s2);
                s2 = fmaf(v.z, v.z, s2); s2 = fmaf(v.w, v.w, s2);
            }
            s  = warp_sum(s);
            s2 = warp_sum(s2);
            if (lane == 0) {
                float mu  = s * (1.f / IND);
                float var = s2 * (1.f / IND) - mu * mu;
                g_mu[row] = mu;
                g_rs[row] = rsqrtf(var + 1e-5f);
            }
        }
    }

    __shared__ __align__(16) float xs[2][64];
    __shared__ __align__(16) float eqs[2][64], eks[2][64];
    __shared__ __align__(16) float redq[2][4], redk[2][4];
    __shared__ __align__(16) float beta_s[2][4];

    // register-resident fast weights as packed f32x2 pairs (16 each)
    ull wy2[16], wq2[16], wk2[16];
    {
        const int base = hd * 4096 + r * 64 + cb;   // 16B-aligned
        const ulonglong2* py = (const ulonglong2*)(Wy0 + base);
        const ulonglong2* pq = (const ulonglong2*)(Wq0 + base);
        const ulonglong2* pk = (const ulonglong2*)(Wk0 + base);
        #pragma unroll
        for (int j = 0; j < 8; j++) {
            ulonglong2 vy = py[j]; wy2[2*j] = vy.x; wy2[2*j+1] = vy.y;
            ulonglong2 vq = pq[j]; wq2[2*j] = vq.x; wq2[2*j+1] = vq.y;
            ulonglong2 vk = pk[j]; wk2[2*j] = vk.x; wk2[2*j+1] = vk.y;
        }
    }
    // wb: global layout (hd, j=64, c=4). Warp c owns column c.
    float wbl = wb0[hd * 256 + lane * 4 + warp];
    float wbh = wb0[hd * 256 + (lane + 32) * 4 + warp];

    const float* hp = h    + (size_t)b * IND + hd * 64;
    float*       yp = g_ys + (size_t)b * IND + hd * 64;
    const int    stride = BSZ * IND;

    // preload x[0]; prefetch x[1] into regs
    if (tid < 64) xs[0][tid] = hp[tid];
    float nx = (tid < 64) ? __ldg(hp + stride + tid) : 0.f;
    __syncthreads();

    for (int t = 0; t < SLEN; ++t) {
        const int p  = t & 1;
        const int pn = p ^ 1;

        // ================= Phase A (reads xs[p]) =================
        ull ayA = 0ull, ayB = 0ull, aqA = 0ull, aqB = 0ull, akA = 0ull, akB = 0ull;
        #pragma unroll
        for (int j = 0; j < 8; j++) {
            ull x2a = *(const ull*)&xs[p][cb + 2*j];
            ull x2b = *(const ull*)&xs[p][cb + 16 + 2*j];
            ayA = ffma2(wy2[j], x2a, ayA);  ayB = ffma2(wy2[j+8], x2b, ayB);
            aqA = ffma2(wq2[j], x2a, aqA);  aqB = ffma2(wq2[j+8], x2b, aqB);
            akA = ffma2(wk2[j], x2a, akA);  akB = ffma2(wk2[j+8], x2b, akB);
        }
        ull ay = fadd2(ayA, ayB), aq = fadd2(aqA, aqB), ak = fadd2(akA, akB);
        float zy, zq, zk, hi_;
        unpack2(ay, zy, hi_); zy += hi_;
        unpack2(aq, zq, hi_); zq += hi_;
        unpack2(ak, zk, hi_); zk += hi_;
        // partner lane (same row, other half): single shfl completes row sum
        zy += __shfl_xor_sync(0xffffffffu, zy, 1);
        zq += __shfl_xor_sync(0xffffffffu, zq, 1);
        zk += __shfl_xor_sync(0xffffffffu, zk, 1);

        float eq = __expf(zq), ek = __expf(zk);
        // eq/ek uniform within lane pairs -> 4-shfl warp row-sum
        float sq = warp_sum_pairs(eq);
        float sk = warp_sum_pairs(ek);
        if (lane == 0) { redq[p][warp] = sq; redk[p][warp] = sk; }
        if (hf == 0) {
            eqs[p][r] = eq; eks[p][r] = ek;
            yp[(size_t)t * stride + r] = zy;      // y output (pre-update Wy)
        }
        // beta_c = sigmoid(wb[:,c]^T x) — warp c, private wb regs
        {
            float pb = fmaf(wbl, xs[p][lane], wbh * xs[p][lane + 32]);
            pb = warp_sum(pb);
            if (lane == 0) beta_s[p][warp] = 1.f / (1.f + __expf(-pb));
        }
        if (tid < 64 && t + 1 < SLEN) xs[pn][tid] = nx;   // publish x[t+1]
        __syncthreads();   // single barrier per step

        // ============ Phase B (reads bank p, writes regs only) ============
        // prefetch x[t+2]: full B+A window to cover L2 latency
        if (tid < 64 && t + 2 < SLEN) nx = __ldg(hp + (size_t)(t + 2) * stride + tid);

        float stq = (redq[p][0] + redq[p][1]) + (redq[p][2] + redq[p][3]);
        float stk = (redk[p][0] + redk[p][1]) + (redk[p][2] + redk[p][3]);
        float invq = __fdividef(1.f, stq);
        float invk = __fdividef(1.f, stk);
        ull invq2  = pack2(invq, invq);
        ull invk2  = pack2(invk, invk);
        ull ninvk2 = pack2(-invk, -invk);

        // dv = W (q - k), qmk formed locally from numerators
        ull dyA = 0ull, dyB = 0ull, dqA = 0ull, dqB = 0ull, dkA = 0ull, dkB = 0ull;
        ull ek2[16];
        #pragma unroll
        for (int j = 0; j < 8; j++) {
            ull eqa = *(const ull*)&eqs[p][cb + 2*j];
            ull eqb = *(const ull*)&eqs[p][cb + 16 + 2*j];
            ek2[j]   = *(const ull*)&eks[p][cb + 2*j];
            ek2[j+8] = *(const ull*)&eks[p][cb + 16 + 2*j];
            ull mka = ffma2(ek2[j],   ninvk2, fmul2(eqa, invq2));
            ull mkb = ffma2(ek2[j+8], ninvk2, fmul2(eqb, invq2));
            dyA = ffma2(wy2[j], mka, dyA);  dyB = ffma2(wy2[j+8], mkb, dyB);
            dqA = ffma2(wq2[j], mka, dqA);  dqB = ffma2(wq2[j+8], mkb, dqB);
            dkA = ffma2(wk2[j], mka, dkA);  dkB = ffma2(wk2[j+8], mkb, dkB);
        }
        ull dy2 = fadd2(dyA, dyB), dq2 = fadd2(dqA, dqB), dk2 = fadd2(dkA, dkB);
        float dy, dq, dk;
        unpack2(dy2, dy, hi_); dy += hi_;
        unpack2(dq2, dq, hi_); dq += hi_;
        unpack2(dk2, dk, hi_); dk += hi_;
        dy += __shfl_xor_sync(0xffffffffu, dy, 1);
        dq += __shfl_xor_sync(0xffffffffu, dq, 1);
        dk += __shfl_xor_sync(0xffffffffu, dk, 1);

        // rank-1 updates: W += beta * dv k^T (registers only)
        float a0 = beta_s[p][0] * dy, a1 = beta_s[p][1] * dq, a2 = beta_s[p][2] * dk;
        ull a02 = pack2(a0, a0), a12 = pack2(a1, a1), a22 = pack2(a2, a2);
        #pragma unroll
        for (int j = 0; j < 16; j++) {
            ull kv2 = fmul2(ek2[j], invk2);
            wy2[j] = ffma2(a02, kv2, wy2[j]);
            wq2[j] = ffma2(a12, kv2, wq2[j]);
            wk2[j] = ffma2(a22, kv2, wk2[j]);
        }
        // wb update: warp c computes dvb_c, updates its private column
        {
            float ql = eqs[p][lane]      * invq - eks[p][lane]      * invk;
            float qh = eqs[p][lane + 32] * invq - eks[p][lane + 32] * invk;
            float pd = fmaf(wbl, ql, wbh * qh);
            pd = warp_sum(pd);
            float b3  = beta_s[p][3];
            float kvl = eks[p][lane] * invk, kvh = eks[p][lane + 32] * invk;
            wbl = fmaf(b3 * kvl, pd, wbl);
            wbh = fmaf(b3 * kvh, pd, wbh);
        }
        // no trailing barrier: next phase A reads xs[pn] (covered by the
        // barrier above) and writes only smem bank pn.
    }
}

// ============================================================
// Kernel 2: out = LN(h) + ys @ out_w^T  (fused epilogue)
// 128x128 tile, BK=16, 256 threads, 8x8 per thread, f32x2 FMA.
// Double-buffered smem, ONE barrier per 16-deep k-tile.
// C[m,n] = sum_k ys[m,k] * out_w[n,k]
// ============================================================
__global__ __launch_bounds__(256, 1) void out_gemm_ln_kernel(
    const float* __restrict__ h, const float* __restrict__ W,
    const float* __restrict__ gamma, const float* __restrict__ lbeta,
    float* __restrict__ out)
{
    __shared__ __align__(16) float As[2][16][128];   // 16KB
    __shared__ __align__(16) float Bs[2][16][128];   // 16KB

    const int tid = threadIdx.x;
    const int tx = tid & 15, ty = tid >> 4;
    const int m0 = blockIdx.y * 128, n0 = blockIdx.x * 128;
    const int lrow = tid >> 1, lkg = tid & 1;

    ull acc[8][4];
    #pragma unroll
    for (int i = 0; i < 8; i++)
        #pragma unroll
        for (int j = 0; j < 4; j++) acc[i][j] = 0ull;

    const float* Ag = g_ys + (size_t)(m0 + lrow) * IND + lkg * 8;
    const float* Bg = W    + (size_t)(n0 + lrow) * IND + lkg * 8;

    float4 av0 = *(const float4*)(Ag);
    float4 av1 = *(const float4*)(Ag + 4);
    float4 bv0 = *(const float4*)(Bg);
    float4 bv1 = *(const float4*)(Bg + 4);

    for (int kt = 0; kt < IND / 16; ++kt) {
        const int buf = kt & 1;
        As[buf][lkg*8+0][lrow] = av0.x; As[buf][lkg*8+1][lrow] = av0.y;
        As[buf][lkg*8+2][lrow] = av0.z; As[buf][lkg*8+3][lrow] = av0.w;
        As[buf][lkg*8+4][lrow] = av1.x; As[buf][lkg*8+5][lrow] = av1.y;
        As[buf][lkg*8+6][lrow] = av1.z; As[buf][lkg*8+7][lrow] = av1.w;
        Bs[buf][lkg*8+0][lrow] = bv0.x; Bs[buf][lkg*8+1][lrow] = bv0.y;
        Bs[buf][lkg*8+2][lrow] = bv0.z; Bs[buf][lkg*8+3][lrow] = bv0.w;
        Bs[buf][lkg*8+4][lrow] = bv1.x; Bs[buf][lkg*8+5][lrow] = bv1.y;
        Bs[buf][lkg*8+6][lrow] = bv1.z; Bs[buf][lkg*8+7][lrow] = bv1.w;
        __syncthreads();
        if (kt + 1 < IND / 16) {
            av0 = *(const float4*)(Ag + (kt + 1) * 16);
            av1 = *(const float4*)(Ag + (kt + 1) * 16 + 4);
            bv0 = *(const float4*)(Bg + (kt + 1) * 16);
            bv1 = *(const float4*)(Bg + (kt + 1) * 16 + 4);
        }
        #pragma unroll
        for (int k = 0; k < 16; k++) {
            float4 a0 = *(const float4*)&As[buf][k][ty * 4];
            float4 a1 = *(const float4*)&As[buf][k][64 + ty * 4];
            ulonglong2 B0 = *(const ulonglong2*)&Bs[buf][k][tx * 4];
            ulonglong2 B1 = *(const ulonglong2*)&Bs[buf][k][64 + tx * 4];
            float af[8] = {a0.x, a0.y, a0.z, a0.w, a1.x, a1.y, a1.z, a1.w};
            #pragma unroll
            for (int i = 0; i < 8; i++) {
                ull ad = pack2(af[i], af[i]);
                acc[i][0] = ffma2(ad, B0.x, acc[i][0]);
                acc[i][1] = ffma2(ad, B0.y, acc[i][1]);
                acc[i][2] = ffma2(ad, B1.x, acc[i][2]);
                acc[i][3] = ffma2(ad, B1.y, acc[i][3]);
            }
        }
        // next iter writes buf^1: all reads of buf^1 (kt-1 compute)
        // happened before this iteration's barrier — safe.
    }

    // epilogue: out = acc + (h - mu) * rsig * gamma + beta
    #pragma unroll
    for (int i = 0; i < 8; i++) {
        int m = m0 + ((i < 4) ? (ty * 4 + i) : (64 + ty * 4 + i - 4));
        float muv = g_mu[m], rsv = g_rs[m];
        const float* hrow = h + (size_t)m * IND;
        float* orow = out + (size_t)m * IND;
        #pragma unroll
        for (int j = 0; j < 4; j++) {
            int n = n0 + ((j < 2) ? (tx * 4 + j * 2) : (64 + tx * 4 + (j - 2) * 2));
            float v0, v1;
            unpack2(acc[i][j], v0, v1);
            orow[n]     = v0 + (hrow[n]     - muv) * rsv * gamma[n]     + lbeta[n];
            orow[n + 1] = v1 + (hrow[n + 1] - muv) * rsv * gamma[n + 1] + lbeta[n + 1];
        }
    }
}

// ============================================================
extern "C" void kernel_launch(void* const* d_in, const int* in_sizes, int n_in,
                              void* d_out, int out_size) {
    const float* h   = (const float*)d_in[0];
    const float* Wy  = (const float*)d_in[1];
    const float* Wq  = (const float*)d_in[2];
    const float* Wk  = (const float*)d_in[3];
    const float* wb  = (const float*)d_in[4];
    const float* ow  = (const float*)d_in[5];
    const float* gam = (const float*)d_in[6];
    const float* bet = (const float*)d_in[7];
    float* out = (float*)d_out;

    srwm_scan_kernel<<<BSZ * NH, 128>>>(h, Wy, Wq, Wk, wb);
    out_gemm_ln_kernel<<<dim3(IND / 128, ROWS / 128), 256>>>(h, ow, gam, bet, out);
}